// round 2
// baseline (speedup 1.0000x reference)
#include <cuda_runtime.h>
#include <cstdint>
#include <math.h>

// Shapes
#define BATCH 64
#define ED 512
#define RES 28
#define HW 784           // 28*28
#define WS 7
#define NWIN 16          // 4*4 windows per image
#define NW_TOT 1024      // BATCH*NWIN
#define NH 8
#define KD 16
#define DHEAD 64         // AR*KD
#define QKV_OUT 96       // 2*KD + DHEAD
#define NTOK 49          // WS*WS

#define TOT 25690112     // 64*512*784
#define HID_TOT 51380224 // 64*1024*784

// Scratch (device globals; no allocations allowed)
__device__ float g_a[TOT];
__device__ float g_b[TOT];
__device__ float g_c[TOT];
__device__ float g_h[HID_TOT];

__device__ __forceinline__ float hswish(float x) {
    return x * fminf(fmaxf(x + 3.f, 0.f), 6.f) * (1.f / 6.f);
}

// ---------------------------------------------------------------------------
// Depthwise 3x3 conv (SAME) + residual:  out = x + dwconv(x)
// grid: (ceil(784/256), B*C), block 256
// ---------------------------------------------------------------------------
__global__ void __launch_bounds__(256) dwconv_res_kernel(
                                  const float* __restrict__ x,
                                  const float* __restrict__ w,
                                  const float* __restrict__ bias,
                                  float* __restrict__ out)
{
    int bc = blockIdx.y;
    int c = bc & (ED - 1);
    int pos = blockIdx.x * 256 + threadIdx.x;
    if (pos >= HW) return;
    int h = pos / RES, ww = pos % RES;
    const float* xp = x + (size_t)bc * HW;
    const float* wp = w + c * 9;
    float acc = bias[c];
#pragma unroll
    for (int dy = 0; dy < 3; dy++) {
        int yy = h + dy - 1;
        if (yy < 0 || yy >= RES) continue;
#pragma unroll
        for (int dx = 0; dx < 3; dx++) {
            int xx = ww + dx - 1;
            if (xx < 0 || xx >= RES) continue;
            acc += xp[yy * RES + xx] * wp[dy * 3 + dx];
        }
    }
    out[(size_t)bc * HW + pos] = xp[pos] + acc;
}

// ---------------------------------------------------------------------------
// Generic batched fp32 GEMM: C[z] = A @ Bin[z] (+bias, fused hswish/residual)
//   A: [M,K] row-major (weights), Bin: [Z][K][N], C: [Z][M][N]
// Tiles: 64x64x16, 256 threads, 4x4 register blocking.
// ---------------------------------------------------------------------------
template<bool HSW_IN, bool HSW_OUT, bool RESID>
__global__ void __launch_bounds__(256) gemm_kernel(
                            const float* __restrict__ A,
                            const float* __restrict__ Bin,
                            const float* __restrict__ bias,
                            const float* __restrict__ resid,
                            float* __restrict__ C,
                            int M, int N, int K)
{
    __shared__ float As[16 * 65];
    __shared__ float Bs[16 * 64];
    int z = blockIdx.z;
    int m0 = blockIdx.y * 64;
    int n0 = blockIdx.x * 64;
    const float* Bz = Bin + (size_t)z * K * N;
    int t = threadIdx.x;
    int tx = t & 15, ty = t >> 4;
    float acc[4][4] = {};
    bool full_n = (n0 + 64 <= N);

    for (int k0 = 0; k0 < K; k0 += 16) {
#pragma unroll
        for (int i = 0; i < 4; i++) {
            int lin = t + i * 256;
            int m = lin >> 4, k = lin & 15;
            As[k * 65 + m] = A[(size_t)(m0 + m) * K + (k0 + k)];
        }
        if (full_n) {
#pragma unroll
            for (int i = 0; i < 4; i++) {
                int lin = t + i * 256;
                int k = lin >> 6, n = lin & 63;
                float v = Bz[(size_t)(k0 + k) * N + (n0 + n)];
                if (HSW_IN) v = hswish(v);
                Bs[k * 64 + n] = v;
            }
        } else {
#pragma unroll
            for (int i = 0; i < 4; i++) {
                int lin = t + i * 256;
                int k = lin >> 6, n = lin & 63;
                float v = 0.f;
                if (n0 + n < N) v = Bz[(size_t)(k0 + k) * N + (n0 + n)];
                if (HSW_IN) v = hswish(v);
                Bs[k * 64 + n] = v;
            }
        }
        __syncthreads();
#pragma unroll
        for (int kk = 0; kk < 16; kk++) {
            float4 bv = *reinterpret_cast<const float4*>(&Bs[kk * 64 + tx * 4]);
            float a0 = As[kk * 65 + ty * 4 + 0];
            float a1 = As[kk * 65 + ty * 4 + 1];
            float a2 = As[kk * 65 + ty * 4 + 2];
            float a3 = As[kk * 65 + ty * 4 + 3];
            acc[0][0] += a0 * bv.x; acc[0][1] += a0 * bv.y; acc[0][2] += a0 * bv.z; acc[0][3] += a0 * bv.w;
            acc[1][0] += a1 * bv.x; acc[1][1] += a1 * bv.y; acc[1][2] += a1 * bv.z; acc[1][3] += a1 * bv.w;
            acc[2][0] += a2 * bv.x; acc[2][1] += a2 * bv.y; acc[2][2] += a2 * bv.z; acc[2][3] += a2 * bv.w;
            acc[3][0] += a3 * bv.x; acc[3][1] += a3 * bv.y; acc[3][2] += a3 * bv.z; acc[3][3] += a3 * bv.w;
        }
        __syncthreads();
    }

#pragma unroll
    for (int i = 0; i < 4; i++) {
        int m = m0 + ty * 4 + i;
        float bval = bias[m];
#pragma unroll
        for (int j = 0; j < 4; j++) {
            int n = n0 + tx * 4 + j;
            if (n < N) {
                float v = acc[i][j] + bval;
                if (HSW_OUT) v = hswish(v);
                size_t o = (size_t)z * M * N + (size_t)m * N + n;
                if (RESID) v += resid[o];
                C[o] = v;
            }
        }
    }
}

// ---------------------------------------------------------------------------
// Cascaded window attention. One block per window (1024 blocks, 256 threads).
// 8 heads sequential (cascade), everything in dynamic shared memory.
// Input: t [B,512,28,28]; Output: [NW_TOT, 512, 49] (pre-hardswish head concat)
// ---------------------------------------------------------------------------
#define ATTN_SMEM_FLOATS (64*49 + 96*49 + 16*49 + 49*49 + 96*64 + 96 + 49)
#define ATTN_SMEM_BYTES  (ATTN_SMEM_FLOATS * 4)

__global__ void __launch_bounds__(256) attn_kernel(
                            const float* __restrict__ xin,
                            const float* __restrict__ qkv_w,   // [8,96,64]
                            const float* __restrict__ qkv_b,   // [8,96]
                            const float* __restrict__ w7, const float* __restrict__ b7,
                            const float* __restrict__ w5, const float* __restrict__ b5,
                            const float* __restrict__ w3, const float* __restrict__ b3,
                            const float* __restrict__ attn_bias, // [8,49]
                            float* __restrict__ out)             // [1024,512,49]
{
    extern __shared__ float smem[];
    float* sp  = smem;                 // [64][49]
    float* y   = sp  + 64 * 49;        // [96][49]  (q|k|v)
    float* qc  = y   + 96 * 49;        // [16][49]
    float* att = qc  + 16 * 49;        // [49][49]
    float* wsm = att + 49 * 49;        // [96*64]
    float* bsm = wsm + 96 * 64;        // [96]
    float* bia = bsm + 96;             // [49]

    int w = blockIdx.x;
    int b = w >> 4, wy = (w >> 2) & 3, wx = w & 3;
    int t = threadIdx.x;
    const float* xb = xin + (size_t)b * ED * HW;

    for (int head = 0; head < NH; head++) {
        // stage weights/bias
        for (int i = t; i < QKV_OUT * DHEAD; i += 256) wsm[i] = qkv_w[head * QKV_OUT * DHEAD + i];
        if (t < QKV_OUT) bsm[t] = qkv_b[head * QKV_OUT + t];
        if (t < NTOK)    bia[t] = attn_bias[head * NTOK + t];
        // cascade input update
        for (int i = t; i < DHEAD * NTOK; i += 256) {
            int c = i / NTOK, n = i % NTOK;
            int iy = n / WS, ix = n % WS;
            float xv = xb[(size_t)(head * DHEAD + c) * HW + (wy * WS + iy) * RES + (wx * WS + ix)];
            sp[i] = (head == 0) ? xv : sp[i] + xv;
        }
        __syncthreads();
        // y = Wqkv @ sp + b   [96,49]
        for (int o = t; o < QKV_OUT * NTOK; o += 256) {
            int m = o / NTOK, n = o % NTOK;
            float acc = bsm[m];
            const float* wr = &wsm[m * DHEAD];
#pragma unroll 8
            for (int c = 0; c < DHEAD; c++) acc += wr[c] * sp[c * NTOK + n];
            y[o] = acc;
        }
        __syncthreads();
        // depthwise conv on q (rows 0..15 of y)
        int ksz; const float* dw; const float* db;
        if (head == 0)      { ksz = 7; dw = w7; db = b7; }
        else if (head == 1) { ksz = 5; dw = w5; db = b5; }
        else                { ksz = 3; dw = w3 + (head - 2) * KD * 9; db = b3 + (head - 2) * KD; }
        int pad = ksz >> 1;
        for (int o = t; o < KD * NTOK; o += 256) {
            int c = o / NTOK, n = o % NTOK;
            int iy = n / WS, ix = n % WS;
            float acc = db[c];
            for (int dy = 0; dy < ksz; dy++) {
                int yy = iy + dy - pad;
                if (yy < 0 || yy >= WS) continue;
                for (int dx = 0; dx < ksz; dx++) {
                    int xx = ix + dx - pad;
                    if (xx < 0 || xx >= WS) continue;
                    acc += y[c * NTOK + yy * WS + xx] * dw[c * ksz * ksz + dy * ksz + dx];
                }
            }
            qc[o] = acc;
        }
        __syncthreads();
        // attention scores  att[n][m] = 0.25*q.k + bias(|dy|,|dx|)
        for (int o = t; o < NTOK * NTOK; o += 256) {
            int n = o / NTOK, m = o % NTOK;
            float acc = 0.f;
#pragma unroll
            for (int c = 0; c < KD; c++) acc += qc[c * NTOK + n] * y[(KD + c) * NTOK + m];
            int ny = n / WS, nx = n % WS, my = m / WS, mx = m % WS;
            att[o] = acc * 0.25f + bia[abs(ny - my) * WS + abs(nx - mx)];
        }
        __syncthreads();
        // softmax over m (one thread per row)
        if (t < NTOK) {
            float mx = -1e30f;
            for (int m = 0; m < NTOK; m++) mx = fmaxf(mx, att[t * NTOK + m]);
            float s = 0.f;
            for (int m = 0; m < NTOK; m++) { float e = expf(att[t * NTOK + m] - mx); att[t * NTOK + m] = e; s += e; }
            float inv = 1.f / s;
            for (int m = 0; m < NTOK; m++) att[t * NTOK + m] *= inv;
        }
        __syncthreads();
        // out[d][n] = sum_m v[d][m] * att[n][m]; also feeds next cascade stage
        float* outw = out + ((size_t)w * (NH * DHEAD) + head * DHEAD) * NTOK;
        for (int o = t; o < DHEAD * NTOK; o += 256) {
            int d = o / NTOK, n = o % NTOK;
            float acc = 0.f;
#pragma unroll 7
            for (int m = 0; m < NTOK; m++) acc += y[(2 * KD + d) * NTOK + m] * att[n * NTOK + m];
            outw[d * NTOK + n] = acc;
            sp[o] = acc;
        }
        __syncthreads();
    }
}

// ---------------------------------------------------------------------------
// Window merge + residual: out[b,c,h,w] = resid[b,c,h,w] + proj[win,c,iy*7+ix]
// ---------------------------------------------------------------------------
__global__ void __launch_bounds__(256) merge_res_kernel(
                                 const float* __restrict__ resid,
                                 const float* __restrict__ proj,
                                 float* __restrict__ out)
{
    size_t idx = (size_t)blockIdx.x * 256 + threadIdx.x;
    if (idx >= (size_t)TOT) return;
    int pos = (int)(idx % HW);
    int c = (int)((idx / HW) % ED);
    int b = (int)(idx / ((size_t)HW * ED));
    int h = pos / RES, x = pos % RES;
    int wy = h / WS, iy = h % WS, wx = x / WS, ix = x % WS;
    int win = (b * 4 + wy) * 4 + wx;
    out[idx] = resid[idx] + proj[((size_t)win * ED + c) * NTOK + iy * WS + ix];
}

// ---------------------------------------------------------------------------
extern "C" void kernel_launch(void* const* d_in, const int* in_sizes, int n_in,
                              void* d_out, int out_size)
{
    const float* x        = (const float*)d_in[0];
    const float* dw0_w    = (const float*)d_in[1];
    const float* dw0_b    = (const float*)d_in[2];
    const float* ffn0_w1  = (const float*)d_in[3];
    const float* ffn0_b1  = (const float*)d_in[4];
    const float* ffn0_w2  = (const float*)d_in[5];
    const float* ffn0_b2  = (const float*)d_in[6];
    const float* qkv_w    = (const float*)d_in[7];
    const float* qkv_b    = (const float*)d_in[8];
    const float* dwq_w7   = (const float*)d_in[9];
    const float* dwq_b7   = (const float*)d_in[10];
    const float* dwq_w5   = (const float*)d_in[11];
    const float* dwq_b5   = (const float*)d_in[12];
    const float* dwq_w3   = (const float*)d_in[13];
    const float* dwq_b3   = (const float*)d_in[14];
    const float* attn_bias= (const float*)d_in[15];
    const float* proj_w   = (const float*)d_in[16];
    const float* proj_b   = (const float*)d_in[17];
    const float* dw1_w    = (const float*)d_in[18];
    const float* dw1_b    = (const float*)d_in[19];
    const float* ffn1_w1  = (const float*)d_in[20];
    const float* ffn1_b1  = (const float*)d_in[21];
    const float* ffn1_w2  = (const float*)d_in[22];
    const float* ffn1_b2  = (const float*)d_in[23];

    float *pa, *pb, *pc, *ph;
    cudaGetSymbolAddress((void**)&pa, g_a);
    cudaGetSymbolAddress((void**)&pb, g_b);
    cudaGetSymbolAddress((void**)&pc, g_c);
    cudaGetSymbolAddress((void**)&ph, g_h);

    cudaFuncSetAttribute(attn_kernel, cudaFuncAttributeMaxDynamicSharedMemorySize, ATTN_SMEM_BYTES);

    dim3 dwgrid((HW + 255) / 256, BATCH * ED);

    // Stage 1: a = x + dwconv(x)
    dwconv_res_kernel<<<dwgrid, 256>>>(x, dw0_w, dw0_b, pa);
    // Stage 2: h = hswish(W1 a + b1); b = a + W2 h + b2
    gemm_kernel<false, true, false><<<dim3(13, 16, BATCH), 256>>>(ffn0_w1, pa, ffn0_b1, nullptr, ph, 1024, HW, 512);
    gemm_kernel<false, false, true><<<dim3(13, 8, BATCH), 256>>>(ffn0_w2, ph, ffn0_b2, pa, pb, 512, HW, 1024);
    // Stage 3: cascaded window attention -> c [1024,512,49]
    attn_kernel<<<NW_TOT, 256, ATTN_SMEM_BYTES>>>(pb, qkv_w, qkv_b, dwq_w7, dwq_b7, dwq_w5, dwq_b5,
                                                  dwq_w3, dwq_b3, attn_bias, pc);
    // Stage 4: proj on hswish(c) -> a [1024,512,49]
    gemm_kernel<true, false, false><<<dim3(1, 8, NW_TOT), 256>>>(proj_w, pc, proj_b, nullptr, pa, 512, NTOK, 512);
    // Stage 5: c = b + merge(a)
    merge_res_kernel<<<(TOT + 255) / 256, 256>>>(pb, pa, pc);
    // Stage 6: b = c + dwconv(c)
    dwconv_res_kernel<<<dwgrid, 256>>>(pc, dw1_w, dw1_b, pb);
    // Stage 7: h = hswish(W1' b + b1'); out = b + W2' h + b2'
    gemm_kernel<false, true, false><<<dim3(13, 16, BATCH), 256>>>(ffn1_w1, pb, ffn1_b1, nullptr, ph, 1024, HW, 512);
    gemm_kernel<false, false, true><<<dim3(13, 8, BATCH), 256>>>(ffn1_w2, ph, ffn1_b2, pb, (float*)d_out, 512, HW, 1024);
}